// round 5
// baseline (speedup 1.0000x reference)
#include <cuda_runtime.h>
#include <cstddef>

// ---------------- problem constants ----------------
#define N_EMB 250000
#define D     128
#define N_IDX 65536

static constexpr float LR  = 1e-3f;
static constexpr float B1  = 0.9f;
static constexpr float B2  = 0.999f;
static constexpr float EPS = 1e-8f;

// ---------------- scratch (static device globals; no allocation in launch) ----
__device__ int           g_counts[N_EMB];
__device__ unsigned char g_owner[N_IDX];
__device__ float         g_gsum[(size_t)N_EMB * D];

// ---------------- helpers ----------------
__device__ __forceinline__ float adam_std(float g, float m, float p,
                                          float c1, float invd2) {
    float mn = B1 * m + (1.0f - B1) * g;
    float pn = B2 * p + (1.0f - B2) * g * g;
    return c1 * mn / (sqrtf(pn * invd2) + EPS);
}

// Compute the full updated float4 for one row chunk.
__device__ __forceinline__ float4 adam_row(float4 e, float4 g, float4 m, float4 p,
                                           float s) {
    float d1 = 1.0f - powf(B1, s);
    float d2 = 1.0f - powf(B2, s);
    float c1    = LR / d1;
    float invd2 = 1.0f / d2;
    float4 o;
    o.x = e.x - adam_std(g.x, m.x, p.x, c1, invd2);
    o.y = e.y - adam_std(g.y, m.y, p.y, c1, invd2);
    o.z = e.z - adam_std(g.z, m.z, p.z, c1, invd2);
    o.w = e.w - adam_std(g.w, m.w, p.w, c1, invd2);
    return o;
}

// ---------------- kernels ----------------

// 1) zero the per-row occurrence counts (vectorized int4)
__global__ void k_zero_counts() {
    int i = blockIdx.x * blockDim.x + threadIdx.x;
    if (i < N_EMB / 4)
        reinterpret_cast<int4*>(g_counts)[i] = make_int4(0, 0, 0, 0);
}

// 2) histogram + ownership: occurrence that first touches a row owns it
__global__ void k_count(const int* __restrict__ idx) {
    int i = blockIdx.x * blockDim.x + threadIdx.x;
    if (i >= N_IDX) return;
    int old = atomicAdd(&g_counts[idx[i]], 1);
    g_owner[i] = (old == 0) ? 1 : 0;
}

// 3) zero gsum rows that have duplicates (count > 1); one warp per occurrence
__global__ void k_zero_dup_rows(const int* __restrict__ idx) {
    int w    = (blockIdx.x * blockDim.x + threadIdx.x) >> 5;
    int lane = threadIdx.x & 31;
    if (w >= N_IDX) return;
    int row = idx[w];
    if (g_counts[row] <= 1) return; // warp-uniform
    *reinterpret_cast<float4*>(g_gsum + (size_t)row * D + lane * 4) =
        make_float4(0.f, 0.f, 0.f, 0.f);
}

// 4) fused scatter + Adam for singleton rows; atomic scatter for dup rows.
//    One warp per occurrence, lane handles 4 consecutive floats.
__global__ void __launch_bounds__(256)
k_fused(const int*   __restrict__ idx,
        const float* __restrict__ grad,
        const float* __restrict__ emb,
        const float* __restrict__ stepv,
        const float* __restrict__ mem,
        const float* __restrict__ pw,
        float*       __restrict__ out) {
    int w    = (blockIdx.x * blockDim.x + threadIdx.x) >> 5;
    int lane = threadIdx.x & 31;
    if (w >= N_IDX) return;

    int row = idx[w];
    // issue grad load early (independent of counts)
    float4 g = *reinterpret_cast<const float4*>(grad + (size_t)w * D + lane * 4);
    int c = g_counts[row];

    size_t base = (size_t)row * D + (size_t)lane * 4;
    if (c == 1) {
        // full Adam update in-warp: gradient mean == grad
        float4 e = *reinterpret_cast<const float4*>(emb + base);
        float4 m = *reinterpret_cast<const float4*>(mem + base);
        float4 p = *reinterpret_cast<const float4*>(pw  + base);
        float  s = stepv[row] + 1.0f;
        *reinterpret_cast<float4*>(out + base) = adam_row(e, g, m, p, s);
    } else {
        float* dst = g_gsum + base;
        atomicAdd(dst + 0, g.x);
        atomicAdd(dst + 1, g.y);
        atomicAdd(dst + 2, g.z);
        atomicAdd(dst + 3, g.w);
    }
}

// 5) Adam update for duplicate rows: only the owning occurrence works,
//    so exactly one warp per unique dup row.
__global__ void __launch_bounds__(256)
k_dup_update(const int*   __restrict__ idx,
             const float* __restrict__ emb,
             const float* __restrict__ stepv,
             const float* __restrict__ mem,
             const float* __restrict__ pw,
             float*       __restrict__ out) {
    int w    = (blockIdx.x * blockDim.x + threadIdx.x) >> 5;
    int lane = threadIdx.x & 31;
    if (w >= N_IDX) return;
    if (!g_owner[w]) return;        // warp-uniform (all lanes read same flag)
    int row = idx[w];
    int c   = g_counts[row];
    if (c <= 1) return;             // singleton handled in k_fused

    size_t base = (size_t)row * D + (size_t)lane * 4;
    float inv = 1.0f / (float)c;
    float4 g = *reinterpret_cast<const float4*>(g_gsum + base);
    float4 e = *reinterpret_cast<const float4*>(emb + base);
    float4 m = *reinterpret_cast<const float4*>(mem + base);
    float4 p = *reinterpret_cast<const float4*>(pw  + base);
    float  s = stepv[row] + 1.0f;
    g.x *= inv; g.y *= inv; g.z *= inv; g.w *= inv;
    *reinterpret_cast<float4*>(out + base) = adam_row(e, g, m, p, s);
}

// 6) untouched rows: straight copy emb -> out. One warp per row.
__global__ void __launch_bounds__(256)
k_copy_untouched(const float* __restrict__ emb,
                 float*       __restrict__ out) {
    int row  = (blockIdx.x * blockDim.x + threadIdx.x) >> 5;
    int lane = threadIdx.x & 31;
    if (row >= N_EMB) return;
    if (g_counts[row] != 0) return; // warp-uniform
    size_t base = (size_t)row * D + (size_t)lane * 4;
    *reinterpret_cast<float4*>(out + base) =
        *reinterpret_cast<const float4*>(emb + base);
}

// ---------------- launch ----------------
extern "C" void kernel_launch(void* const* d_in, const int* in_sizes, int n_in,
                              void* d_out, int out_size) {
    const int*   idx   = (const int*)  d_in[0];
    const float* grad  = (const float*)d_in[1];
    const float* emb   = (const float*)d_in[2];
    const float* stepv = (const float*)d_in[3];
    const float* mem   = (const float*)d_in[4];
    const float* pw    = (const float*)d_in[5];
    float* out = (float*)d_out;

    // warp-per-occurrence grids: 65536 warps = 2,097,152 threads
    const int OCC_BLOCKS = (N_IDX * 32) / 256;         // 8192
    // warp-per-row grid: 250000 warps = 8,000,000 threads
    const int ROW_BLOCKS = (N_EMB * 32 + 255) / 256;   // 31250

    k_zero_counts<<<(N_EMB / 4 + 255) / 256, 256>>>();
    k_count<<<(N_IDX + 255) / 256, 256>>>(idx);
    k_zero_dup_rows<<<OCC_BLOCKS, 256>>>(idx);
    k_fused<<<OCC_BLOCKS, 256>>>(idx, grad, emb, stepv, mem, pw, out);
    k_dup_update<<<OCC_BLOCKS, 256>>>(idx, emb, stepv, mem, pw, out);
    k_copy_untouched<<<ROW_BLOCKS, 256>>>(emb, out);
}

// round 6
// speedup vs baseline: 1.1477x; 1.1477x over previous
#include <cuda_runtime.h>
#include <cstddef>

// ---------------- problem constants ----------------
#define N_EMB 250000
#define D     128
#define N_IDX 65536

static constexpr float LR  = 1e-3f;
static constexpr float B1  = 0.9f;
static constexpr float B2  = 0.999f;
static constexpr float EPS = 1e-8f;

// ---------------- scratch (static device globals; no allocation in launch) ----
__device__ int   g_counts[N_EMB];
__device__ int   g_first[N_EMB];     // occurrence index of first touch (valid where count>0)
__device__ float g_gsum[(size_t)N_EMB * D];   // used only for duplicate rows

// ---------------- helpers ----------------
__device__ __forceinline__ float adam_std(float g, float m, float p,
                                          float c1, float invd2) {
    float mn = B1 * m + (1.0f - B1) * g;
    float pn = B2 * p + (1.0f - B2) * g * g;
    return c1 * mn / (sqrtf(pn * invd2) + EPS);
}

__device__ __forceinline__ float4 adam_row(float4 e, float4 g, float4 m, float4 p,
                                           float s) {
    float d1 = 1.0f - powf(B1, s);
    float d2 = 1.0f - powf(B2, s);
    float c1    = LR / d1;
    float invd2 = 1.0f / d2;
    float4 o;
    o.x = e.x - adam_std(g.x, m.x, p.x, c1, invd2);
    o.y = e.y - adam_std(g.y, m.y, p.y, c1, invd2);
    o.z = e.z - adam_std(g.z, m.z, p.z, c1, invd2);
    o.w = e.w - adam_std(g.w, m.w, p.w, c1, invd2);
    return o;
}

// ---------------- kernels ----------------

// 1) zero the per-row occurrence counts (vectorized int4)
__global__ void k_zero_counts() {
    int i = blockIdx.x * blockDim.x + threadIdx.x;
    if (i < N_EMB / 4)
        reinterpret_cast<int4*>(g_counts)[i] = make_int4(0, 0, 0, 0);
}

// 2) histogram; first toucher records its occurrence index
__global__ void k_count(const int* __restrict__ idx) {
    int i = blockIdx.x * blockDim.x + threadIdx.x;
    if (i >= N_IDX) return;
    int row = idx[i];
    int old = atomicAdd(&g_counts[row], 1);
    if (old == 0) g_first[row] = i;   // exactly one occurrence sees old==0
}

// 3) zero gsum rows that have duplicates (count > 1); one warp per occurrence
__global__ void k_zero_dup_rows(const int* __restrict__ idx) {
    int w    = (blockIdx.x * blockDim.x + threadIdx.x) >> 5;
    int lane = threadIdx.x & 31;
    if (w >= N_IDX) return;
    int row = idx[w];
    if (g_counts[row] <= 1) return;   // warp-uniform
    *reinterpret_cast<float4*>(g_gsum + (size_t)row * D + lane * 4) =
        make_float4(0.f, 0.f, 0.f, 0.f);
}

// 4) scatter grads into gsum for DUPLICATE rows only (singletons skip entirely).
__global__ void k_scatter_dup(const int* __restrict__ idx,
                              const float* __restrict__ grad) {
    int w    = (blockIdx.x * blockDim.x + threadIdx.x) >> 5;
    int lane = threadIdx.x & 31;
    if (w >= N_IDX) return;
    int row = idx[w];
    if (g_counts[row] <= 1) return;   // warp-uniform; skip grad load too
    float4 g = *reinterpret_cast<const float4*>(grad + (size_t)w * D + lane * 4);
    float* dst = g_gsum + (size_t)row * D + lane * 4;
    atomicAdd(dst + 0, g.x);
    atomicAdd(dst + 1, g.y);
    atomicAdd(dst + 2, g.z);
    atomicAdd(dst + 3, g.w);
}

// 5) monolithic fused Adam + full-table writeback. One warp per row.
//    c==0: copy. c==1: grad read directly from grad[g_first[row]].
//    c>1 : grad mean read from gsum.
__global__ void __launch_bounds__(256)
k_update(const int*   __restrict__ /*unused*/,
         const float* __restrict__ grad,
         const float* __restrict__ emb,
         const float* __restrict__ stepv,
         const float* __restrict__ mem,
         const float* __restrict__ pw,
         float*       __restrict__ out) {
    int row  = (blockIdx.x * blockDim.x + threadIdx.x) >> 5;
    int lane = threadIdx.x & 31;
    if (row >= N_EMB) return;

    size_t base = (size_t)row * D + (size_t)lane * 4;
    float4 e = *reinterpret_cast<const float4*>(emb + base);
    int    c = g_counts[row];    // broadcast load (all lanes same addr)

    float4 o;
    if (c == 0) {
        o = e;                   // untouched: straight copy
    } else {
        float4 g;
        if (c == 1) {
            int occ = g_first[row];
            g = *reinterpret_cast<const float4*>(grad + (size_t)occ * D + lane * 4);
        } else {
            float inv = 1.0f / (float)c;
            g = *reinterpret_cast<const float4*>(g_gsum + base);
            g.x *= inv; g.y *= inv; g.z *= inv; g.w *= inv;
        }
        float4 m = *reinterpret_cast<const float4*>(mem + base);
        float4 p = *reinterpret_cast<const float4*>(pw  + base);
        float  s = stepv[row] + 1.0f;
        o = adam_row(e, g, m, p, s);
    }
    *reinterpret_cast<float4*>(out + base) = o;
}

// ---------------- launch ----------------
extern "C" void kernel_launch(void* const* d_in, const int* in_sizes, int n_in,
                              void* d_out, int out_size) {
    const int*   idx   = (const int*)  d_in[0];
    const float* grad  = (const float*)d_in[1];
    const float* emb   = (const float*)d_in[2];
    const float* stepv = (const float*)d_in[3];
    const float* mem   = (const float*)d_in[4];
    const float* pw    = (const float*)d_in[5];
    float* out = (float*)d_out;

    const int OCC_BLOCKS = (N_IDX * 32) / 256;          // warp per occurrence
    const int ROW_BLOCKS = (N_EMB * 32 + 255) / 256;    // warp per row

    k_zero_counts<<<(N_EMB / 4 + 255) / 256, 256>>>();
    k_count<<<(N_IDX + 255) / 256, 256>>>(idx);
    k_zero_dup_rows<<<OCC_BLOCKS, 256>>>(idx);
    k_scatter_dup<<<OCC_BLOCKS, 256>>>(idx, grad);
    k_update<<<ROW_BLOCKS, 256>>>(idx, grad, emb, stepv, mem, pw, out);
}

// round 7
// speedup vs baseline: 1.2707x; 1.1071x over previous
#include <cuda_runtime.h>
#include <cstddef>

// ---------------- problem constants ----------------
#define N_EMB 250000
#define D     128
#define N_IDX 65536

static constexpr float LR  = 1e-3f;
static constexpr float B1  = 0.9f;
static constexpr float B2  = 0.999f;
static constexpr float EPS = 1e-8f;

// ---------------- scratch (static device globals; zero-initialized) ----------
// g_head[row] = (occurrence index + 1) of most recent toucher, 0 = untouched.
// g_next[occ] = previous head at insertion time (chain link), 0 terminates.
// k_update self-cleans g_head back to 0, so every launch (and every graph
// replay) starts from the identical all-zero state.
__device__ int g_head[N_EMB];
__device__ int g_next[N_IDX];

// ---------------- helpers ----------------
__device__ __forceinline__ float adam_std(float g, float m, float p,
                                          float c1, float invd2) {
    float mn = B1 * m + (1.0f - B1) * g;
    float pn = B2 * p + (1.0f - B2) * g * g;
    return c1 * mn / (sqrtf(pn * invd2) + EPS);
}

__device__ __forceinline__ float4 adam_row(float4 e, float4 g, float4 m, float4 p,
                                           float s) {
    float d1 = 1.0f - powf(B1, s);
    float d2 = 1.0f - powf(B2, s);
    float c1    = LR / d1;
    float invd2 = 1.0f / d2;
    float4 o;
    o.x = e.x - adam_std(g.x, m.x, p.x, c1, invd2);
    o.y = e.y - adam_std(g.y, m.y, p.y, c1, invd2);
    o.z = e.z - adam_std(g.z, m.z, p.z, c1, invd2);
    o.w = e.w - adam_std(g.w, m.w, p.w, c1, invd2);
    return o;
}

// ---------------- kernels ----------------

// 1) build per-row occurrence chains with atomicExch (int, cheap).
__global__ void k_chain(const int* __restrict__ idx) {
    int i = blockIdx.x * blockDim.x + threadIdx.x;
    if (i >= N_IDX) return;
    int row = idx[i];
    int old = atomicExch(&g_head[row], i + 1);
    g_next[i] = old;               // 0 terminates the chain
}

// 2) monolithic fused: chain walk + grad mean + Adam + full-table writeback.
//    One warp per row, lane handles 4 consecutive floats.
__global__ void __launch_bounds__(256)
k_update(const float* __restrict__ grad,
         const float* __restrict__ emb,
         const float* __restrict__ stepv,
         const float* __restrict__ mem,
         const float* __restrict__ pw,
         float*       __restrict__ out) {
    int row  = (blockIdx.x * blockDim.x + threadIdx.x) >> 5;
    int lane = threadIdx.x & 31;
    if (row >= N_EMB) return;

    size_t base = (size_t)row * D + (size_t)lane * 4;
    float4 e = *reinterpret_cast<const float4*>(emb + base);
    int head = g_head[row];        // all lanes same addr -> broadcast

    float4 o;
    if (head == 0) {
        o = e;                     // untouched: straight copy
    } else {
        // walk the occurrence chain, summing grads (avg chain length ~1.26)
        float4 gs = make_float4(0.f, 0.f, 0.f, 0.f);
        int c = 0;
        int occ = head - 1;
        #pragma unroll 1
        while (true) {
            const float4* gp =
                reinterpret_cast<const float4*>(grad + (size_t)occ * D + lane * 4);
            int nxt = g_next[occ];         // uniform load, overlaps with gp load
            float4 g = *gp;
            gs.x += g.x; gs.y += g.y; gs.z += g.z; gs.w += g.w;
            c++;
            if (nxt == 0) break;
            occ = nxt - 1;
        }
        float inv = 1.0f / (float)c;
        gs.x *= inv; gs.y *= inv; gs.z *= inv; gs.w *= inv;

        float4 m = *reinterpret_cast<const float4*>(mem + base);
        float4 p = *reinterpret_cast<const float4*>(pw  + base);
        float  s = stepv[row] + 1.0f;
        o = adam_row(e, gs, m, p, s);

        if (lane == 0) g_head[row] = 0;    // self-clean for next launch/replay
    }
    *reinterpret_cast<float4*>(out + base) = o;
}

// ---------------- launch ----------------
extern "C" void kernel_launch(void* const* d_in, const int* in_sizes, int n_in,
                              void* d_out, int out_size) {
    const int*   idx   = (const int*)  d_in[0];
    const float* grad  = (const float*)d_in[1];
    const float* emb   = (const float*)d_in[2];
    const float* stepv = (const float*)d_in[3];
    const float* mem   = (const float*)d_in[4];
    const float* pw    = (const float*)d_in[5];
    float* out = (float*)d_out;

    const int ROW_BLOCKS = (N_EMB * 32 + 255) / 256;   // warp per row

    k_chain<<<(N_IDX + 255) / 256, 256>>>(idx);
    k_update<<<ROW_BLOCKS, 256>>>(grad, emb, stepv, mem, pw, out);
}

// round 8
// speedup vs baseline: 1.3717x; 1.0795x over previous
#include <cuda_runtime.h>
#include <cstddef>

// ---------------- problem constants ----------------
#define N_EMB 250000
#define D     128
#define N_IDX 65536
#define ROWS_PER_WARP 4          // N_EMB % 4 == 0

static constexpr float LR  = 1e-3f;
static constexpr float B1  = 0.9f;
static constexpr float B2  = 0.999f;
static constexpr float EPS = 1e-8f;

// ---------------- scratch (static device globals; zero-initialized) ----------
// g_head[row] = (occurrence index + 1) of most recent toucher, 0 = untouched.
// g_next[occ] = previous head at insertion time (chain link), 0 terminates.
// k_update self-cleans g_head back to 0, so every launch (and every graph
// replay) starts from the identical all-zero state.
__device__ int g_head[N_EMB];
__device__ int g_next[N_IDX];

// ---------------- helpers ----------------
__device__ __forceinline__ float adam_std(float g, float m, float p,
                                          float c1, float invd2) {
    float mn = B1 * m + (1.0f - B1) * g;
    float pn = B2 * p + (1.0f - B2) * g * g;
    return c1 * mn / (sqrtf(pn * invd2) + EPS);
}

__device__ __forceinline__ float4 adam_row(float4 e, float4 g, float4 m, float4 p,
                                           float s) {
    float d1 = 1.0f - powf(B1, s);
    float d2 = 1.0f - powf(B2, s);
    float c1    = LR / d1;
    float invd2 = 1.0f / d2;
    float4 o;
    o.x = e.x - adam_std(g.x, m.x, p.x, c1, invd2);
    o.y = e.y - adam_std(g.y, m.y, p.y, c1, invd2);
    o.z = e.z - adam_std(g.z, m.z, p.z, c1, invd2);
    o.w = e.w - adam_std(g.w, m.w, p.w, c1, invd2);
    return o;
}

// ---------------- kernels ----------------

// 1) build per-row occurrence chains with atomicExch (int, cheap).
__global__ void k_chain(const int* __restrict__ idx) {
    int i = blockIdx.x * blockDim.x + threadIdx.x;
    if (i >= N_IDX) return;
    int row = idx[i];
    int old = atomicExch(&g_head[row], i + 1);
    g_next[i] = old;               // 0 terminates the chain
}

// Process one row given its preloaded emb chunk and head value.
__device__ __forceinline__ void process_row(
    int row, int lane, int head, float4 e,
    const float* __restrict__ grad,
    const float* __restrict__ stepv,
    const float* __restrict__ mem,
    const float* __restrict__ pw,
    float*       __restrict__ out) {
    size_t base = (size_t)row * D + (size_t)lane * 4;
    float4 o;
    if (head == 0) {
        o = e;                      // untouched: straight copy
    } else {
        // walk the occurrence chain, summing grads (avg chain length ~1.26)
        float4 gs = make_float4(0.f, 0.f, 0.f, 0.f);
        int c = 0;
        int occ = head - 1;
        #pragma unroll 1
        while (true) {
            const float4* gp =
                reinterpret_cast<const float4*>(grad + (size_t)occ * D + lane * 4);
            int nxt = g_next[occ];          // uniform load, overlaps with gp load
            float4 g = __ldcs(gp);
            gs.x += g.x; gs.y += g.y; gs.z += g.z; gs.w += g.w;
            c++;
            if (nxt == 0) break;
            occ = nxt - 1;
        }
        float inv = 1.0f / (float)c;
        gs.x *= inv; gs.y *= inv; gs.z *= inv; gs.w *= inv;

        float4 m = __ldcs(reinterpret_cast<const float4*>(mem + base));
        float4 p = __ldcs(reinterpret_cast<const float4*>(pw  + base));
        float  s = stepv[row] + 1.0f;
        o = adam_row(e, gs, m, p, s);

        if (lane == 0) g_head[row] = 0;     // self-clean for next replay
    }
    __stcs(reinterpret_cast<float4*>(out + base), o);
}

// 2) monolithic fused update. One warp per 4 rows; front-batched loads for MLP.
__global__ void __launch_bounds__(256)
k_update(const float* __restrict__ grad,
         const float* __restrict__ emb,
         const float* __restrict__ stepv,
         const float* __restrict__ mem,
         const float* __restrict__ pw,
         float*       __restrict__ out) {
    int w    = (blockIdx.x * blockDim.x + threadIdx.x) >> 5;
    int lane = threadIdx.x & 31;
    int r0   = w * ROWS_PER_WARP;
    if (r0 >= N_EMB) return;       // N_EMB % ROWS_PER_WARP == 0 -> all 4 valid

    size_t b0 = (size_t)r0 * D + (size_t)lane * 4;

    // front-batch 8 independent loads (4 emb chunks + 4 heads)
    float4 e0 = __ldcs(reinterpret_cast<const float4*>(emb + b0));
    float4 e1 = __ldcs(reinterpret_cast<const float4*>(emb + b0 + D));
    float4 e2 = __ldcs(reinterpret_cast<const float4*>(emb + b0 + 2 * D));
    float4 e3 = __ldcs(reinterpret_cast<const float4*>(emb + b0 + 3 * D));
    int h0 = g_head[r0];
    int h1 = g_head[r0 + 1];
    int h2 = g_head[r0 + 2];
    int h3 = g_head[r0 + 3];

    process_row(r0,     lane, h0, e0, grad, stepv, mem, pw, out);
    process_row(r0 + 1, lane, h1, e1, grad, stepv, mem, pw, out);
    process_row(r0 + 2, lane, h2, e2, grad, stepv, mem, pw, out);
    process_row(r0 + 3, lane, h3, e3, grad, stepv, mem, pw, out);
}

// ---------------- launch ----------------
extern "C" void kernel_launch(void* const* d_in, const int* in_sizes, int n_in,
                              void* d_out, int out_size) {
    const int*   idx   = (const int*)  d_in[0];
    const float* grad  = (const float*)d_in[1];
    const float* emb   = (const float*)d_in[2];
    const float* stepv = (const float*)d_in[3];
    const float* mem   = (const float*)d_in[4];
    const float* pw    = (const float*)d_in[5];
    float* out = (float*)d_out;

    // warps needed: N_EMB / ROWS_PER_WARP = 62500; 8 warps per 256-thread block
    const int N_WARPS    = N_EMB / ROWS_PER_WARP;
    const int ROW_BLOCKS = (N_WARPS + 7) / 8;

    k_chain<<<(N_IDX + 255) / 256, 256>>>(idx);
    k_update<<<ROW_BLOCKS, 256>>>(grad, emb, stepv, mem, pw, out);
}